// round 2
// baseline (speedup 1.0000x reference)
#include <cuda_runtime.h>
#include <cuda_bf16.h>
#include <math.h>

// Problem constants
#define BATCH   4
#define SEQ     8192
#define MROWS   (BATCH * SEQ)   // 32768
#define DIM     256
#define NCLS    1000
#define EPS_F   1e-5f

// GEMM tiling
#define BM 128
#define BN 128
#define BK 8

// Scratch (allocation-free rule: __device__ globals)
__device__ float g_x[MROWS * DIM];       // projected + expmapped features
__device__ float g_xsq[MROWS];           // ||x||^2 per row
__device__ float g_protos[NCLS * DIM];   // expmapped embeddings
__device__ float g_psq[NCLS];            // ||p||^2 per class

// ---------------------------------------------------------------------------
// GEMM1: Y[m,e] = sum_d A[m,d] * W[e,d] + bias[e]   (NT, both K-contiguous)
// M=32768, N=256, K=256. Writes to g_x (expmap applied afterwards in-place).
// ---------------------------------------------------------------------------
__global__ __launch_bounds__(256, 2)
void proj_gemm_kernel(const float* __restrict__ A,
                      const float* __restrict__ W,
                      const float* __restrict__ bias,
                      float* __restrict__ Y)
{
    const int K = DIM, Nn = DIM;
    __shared__ float As[BK][BM];
    __shared__ float Bs[BK][BN];

    const int tid = threadIdx.x;           // 256 threads
    const int m0 = blockIdx.y * BM;
    const int n0 = blockIdx.x * BN;

    const int lr = tid >> 1;               // 0..127 row within tile
    const int lk = (tid & 1) * 4;          // 0 or 4

    const int trow = (tid >> 4) * 8;       // 0..120
    const int tcol = (tid & 15) * 8;       // 0..120

    float acc[8][8];
    #pragma unroll
    for (int i = 0; i < 8; i++)
        #pragma unroll
        for (int j = 0; j < 8; j++) acc[i][j] = 0.f;

    for (int k0 = 0; k0 < K; k0 += BK) {
        float4 av = *(const float4*)&A[(size_t)(m0 + lr) * K + k0 + lk];
        float4 bv = *(const float4*)&W[(size_t)(n0 + lr) * K + k0 + lk];
        As[lk + 0][lr] = av.x; As[lk + 1][lr] = av.y;
        As[lk + 2][lr] = av.z; As[lk + 3][lr] = av.w;
        Bs[lk + 0][lr] = bv.x; Bs[lk + 1][lr] = bv.y;
        Bs[lk + 2][lr] = bv.z; Bs[lk + 3][lr] = bv.w;
        __syncthreads();

        #pragma unroll
        for (int k = 0; k < BK; k++) {
            float4 a0 = *(const float4*)&As[k][trow];
            float4 a1 = *(const float4*)&As[k][trow + 4];
            float4 b0 = *(const float4*)&Bs[k][tcol];
            float4 b1 = *(const float4*)&Bs[k][tcol + 4];
            float a[8] = {a0.x, a0.y, a0.z, a0.w, a1.x, a1.y, a1.z, a1.w};
            float b[8] = {b0.x, b0.y, b0.z, b0.w, b1.x, b1.y, b1.z, b1.w};
            #pragma unroll
            for (int i = 0; i < 8; i++)
                #pragma unroll
                for (int j = 0; j < 8; j++)
                    acc[i][j] = fmaf(a[i], b[j], acc[i][j]);
        }
        __syncthreads();
    }

    #pragma unroll
    for (int i = 0; i < 8; i++) {
        const int m = m0 + trow + i;
        #pragma unroll
        for (int j = 0; j < 8; j++) {
            const int e = n0 + tcol + j;
            Y[(size_t)m * Nn + e] = acc[i][j] + bias[e];
        }
    }
}

// ---------------------------------------------------------------------------
// expmap0 per row: x = tanh(||y||_clamped)/||y||_clamped * y ; also ||x||^2
// One block (256 threads) per row of 256 floats.
// ---------------------------------------------------------------------------
__global__ void expmap_kernel(const float* __restrict__ src,
                              float* __restrict__ dst,
                              float* __restrict__ sq_out)
{
    const int row = blockIdx.x;
    const int tid = threadIdx.x;
    const float v = src[(size_t)row * DIM + tid];

    // block reduction of v*v over 256 threads
    float s = v * v;
    #pragma unroll
    for (int off = 16; off > 0; off >>= 1)
        s += __shfl_xor_sync(0xFFFFFFFFu, s, off);

    __shared__ float warp_s[8];
    __shared__ float total_sh;
    const int warp = tid >> 5;
    if ((tid & 31) == 0) warp_s[warp] = s;
    __syncthreads();
    if (tid == 0) {
        float t = 0.f;
        #pragma unroll
        for (int w = 0; w < 8; w++) t += warp_s[w];
        total_sh = t;
    }
    __syncthreads();

    const float total = total_sh;
    const float norm = sqrtf(total);
    const float cn = fmaxf(norm, EPS_F);
    const float scale = tanhf(cn) / cn;

    dst[(size_t)row * DIM + tid] = scale * v;
    if (tid == 0) sq_out[row] = scale * scale * total;
}

// ---------------------------------------------------------------------------
// GEMM2 + Poincare-distance epilogue:
//   xp[m,c] = sum_d x[m,d] * protos[c,d]
//   out[m,c] = -acosh(max(1 + 2*diff/denom, 1+eps)) * lscale
// M=32768, C=1000, K=256.
// ---------------------------------------------------------------------------
__global__ __launch_bounds__(256, 2)
void logits_gemm_kernel(const float* __restrict__ X,
                        const float* __restrict__ P,
                        const float* __restrict__ xsq,
                        const float* __restrict__ psq,
                        const float* __restrict__ logit_scale,
                        float* __restrict__ Out)
{
    const int K = DIM;
    __shared__ float As[BK][BM];
    __shared__ float Bs[BK][BN];

    const int tid = threadIdx.x;
    const int m0 = blockIdx.y * BM;
    const int n0 = blockIdx.x * BN;

    const int lr = tid >> 1;
    const int lk = (tid & 1) * 4;
    const int trow = (tid >> 4) * 8;
    const int tcol = (tid & 15) * 8;

    float acc[8][8];
    #pragma unroll
    for (int i = 0; i < 8; i++)
        #pragma unroll
        for (int j = 0; j < 8; j++) acc[i][j] = 0.f;

    const bool brow_ok = (n0 + lr) < NCLS;

    for (int k0 = 0; k0 < K; k0 += BK) {
        float4 av = *(const float4*)&X[(size_t)(m0 + lr) * K + k0 + lk];
        float4 bv = make_float4(0.f, 0.f, 0.f, 0.f);
        if (brow_ok)
            bv = *(const float4*)&P[(size_t)(n0 + lr) * K + k0 + lk];
        As[lk + 0][lr] = av.x; As[lk + 1][lr] = av.y;
        As[lk + 2][lr] = av.z; As[lk + 3][lr] = av.w;
        Bs[lk + 0][lr] = bv.x; Bs[lk + 1][lr] = bv.y;
        Bs[lk + 2][lr] = bv.z; Bs[lk + 3][lr] = bv.w;
        __syncthreads();

        #pragma unroll
        for (int k = 0; k < BK; k++) {
            float4 a0 = *(const float4*)&As[k][trow];
            float4 a1 = *(const float4*)&As[k][trow + 4];
            float4 b0 = *(const float4*)&Bs[k][tcol];
            float4 b1 = *(const float4*)&Bs[k][tcol + 4];
            float a[8] = {a0.x, a0.y, a0.z, a0.w, a1.x, a1.y, a1.z, a1.w};
            float b[8] = {b0.x, b0.y, b0.z, b0.w, b1.x, b1.y, b1.z, b1.w};
            #pragma unroll
            for (int i = 0; i < 8; i++)
                #pragma unroll
                for (int j = 0; j < 8; j++)
                    acc[i][j] = fmaf(a[i], b[j], acc[i][j]);
        }
        __syncthreads();
    }

    const float lscale = fminf(expf(*logit_scale), 100.f);

    float xs[8];
    #pragma unroll
    for (int i = 0; i < 8; i++) xs[i] = xsq[m0 + trow + i];

    #pragma unroll
    for (int j = 0; j < 8; j++) {
        const int c = n0 + tcol + j;
        if (c >= NCLS) continue;
        const float ps = psq[c];
        const float one_m_ps = 1.f - ps;
        #pragma unroll
        for (int i = 0; i < 8; i++) {
            const int m = m0 + trow + i;
            const float xp = acc[i][j];
            const float diff = fmaxf(xs[i] + ps - 2.f * xp, 0.f);
            const float denom = fmaxf((1.f - xs[i]) * one_m_ps, EPS_F);
            const float arg = fmaxf(1.f + 2.f * diff / denom, 1.f + EPS_F);
            Out[(size_t)m * NCLS + c] = -acoshf(arg) * lscale;
        }
    }
}

// ---------------------------------------------------------------------------
// Launch
// Inputs (metadata order): features[4,8192,256], W[256,256], b[256],
//                          embeddings[1000,256], logit_scale[]
// Output: float32 [4,8192,1000]
// ---------------------------------------------------------------------------
extern "C" void kernel_launch(void* const* d_in, const int* in_sizes, int n_in,
                              void* d_out, int out_size)
{
    const float* features    = (const float*)d_in[0];
    const float* W           = (const float*)d_in[1];
    const float* bias        = (const float*)d_in[2];
    const float* embeddings  = (const float*)d_in[3];
    const float* logit_scale = (const float*)d_in[4];
    float* out = (float*)d_out;

    float *x, *xsq, *protos, *psq;
    cudaGetSymbolAddress((void**)&x,      g_x);
    cudaGetSymbolAddress((void**)&xsq,    g_xsq);
    cudaGetSymbolAddress((void**)&protos, g_protos);
    cudaGetSymbolAddress((void**)&psq,    g_psq);

    // 1. Projection GEMM: g_x = features @ W^T + b
    {
        dim3 grid(DIM / BN, MROWS / BM);  // (2, 256)
        proj_gemm_kernel<<<grid, 256>>>(features, W, bias, x);
    }
    // 2. expmap0 on projected features (in place) + row norms
    expmap_kernel<<<MROWS, DIM>>>(x, x, xsq);
    // 3. expmap0 on embeddings -> protos + norms
    expmap_kernel<<<NCLS, DIM>>>(embeddings, protos, psq);
    // 4. Logits GEMM + Poincare distance epilogue
    {
        dim3 grid((NCLS + BN - 1) / BN, MROWS / BM);  // (8, 256)
        logits_gemm_kernel<<<grid, 256>>>(x, protos, xsq, psq, logit_scale, out);
    }
}

// round 3
// speedup vs baseline: 3.3945x; 3.3945x over previous
#include <cuda_runtime.h>
#include <cuda_bf16.h>
#include <math.h>
#include <stdint.h>

// Problem constants
#define BATCH   4
#define SEQ     8192
#define MROWS   (BATCH * SEQ)   // 32768
#define DIM     256
#define NCLS    1000
#define EPS_F   1e-5f

// MMA tiling: 128x128 CTA tile, BK=32, 8 warps (4 in M x 2 in N), warp tile 32x64
#define BM 128
#define BN 128
#define BK 32
#define LDS_PAD 8
#define LDT (BK + LDS_PAD)      // 40 bf16 elems: 80B row stride -> conflict-free frag loads

// Scratch (allocation-free rule: __device__ globals)
__device__ __nv_bfloat16 g_featb[MROWS * DIM];   // features in bf16
__device__ __nv_bfloat16 g_Wb[DIM * DIM];        // W in bf16
__device__ float         g_y[MROWS * DIM];       // projection output (fp32)
__device__ __nv_bfloat16 g_xb[MROWS * DIM];      // expmapped features (bf16)
__device__ float         g_xsq[MROWS];           // ||x||^2
__device__ __nv_bfloat16 g_pb[NCLS * DIM];       // expmapped prototypes (bf16)
__device__ float         g_psq[NCLS];            // ||p||^2

// ---------------------------------------------------------------------------
// fp32 -> bf16 elementwise convert (4 elems / thread)
// ---------------------------------------------------------------------------
__global__ void f2b_kernel(const float* __restrict__ in,
                           __nv_bfloat16* __restrict__ out, int n)
{
    int i = (blockIdx.x * blockDim.x + threadIdx.x) * 4;
    if (i < n) {
        float4 v = *(const float4*)(in + i);
        __nv_bfloat162 lo = __floats2bfloat162_rn(v.x, v.y);
        __nv_bfloat162 hi = __floats2bfloat162_rn(v.z, v.w);
        uint2 pk;
        pk.x = *(uint32_t*)&lo;
        pk.y = *(uint32_t*)&hi;
        *(uint2*)(out + i) = pk;
    }
}

// ---------------------------------------------------------------------------
// Shared MMA mainloop: acc[2][8][4] += A[m0:m0+128, :] * B[n0:n0+128, :]^T
// A, B are bf16, K-contiguous with row stride DIM. B rows >= Brows are zero.
// 256 threads. mma.sync.m16n8k16.row.col.f32.bf16.bf16.f32
// ---------------------------------------------------------------------------
__device__ __forceinline__ void mma_mainloop(
    const __nv_bfloat16* __restrict__ Ag,
    const __nv_bfloat16* __restrict__ Bg,
    int m0, int n0, int Brows,
    float acc[2][8][4],
    __nv_bfloat16 (*As)[LDT], __nv_bfloat16 (*Bs)[LDT])
{
    const int tid  = threadIdx.x;
    const int warp = tid >> 5;
    const int lane = tid & 31;
    const int wm = (warp & 3) * 32;    // warp row offset (4 warps in M)
    const int wn = (warp >> 2) * 64;   // warp col offset (2 warps in N)
    const int g  = lane >> 2;          // group id 0..7
    const int tg = lane & 3;           // thread in group 0..3

    for (int k0 = 0; k0 < DIM; k0 += BK) {
        // ---- global -> smem: 128 rows x 32 halves (64B/row), 16B per thread x2
        #pragma unroll
        for (int r = 0; r < 2; r++) {
            int idx = tid + r * 256;
            int row = idx >> 2;
            int ch  = (idx & 3) * 8;
            uint4 v = *(const uint4*)&Ag[(size_t)(m0 + row) * DIM + k0 + ch];
            *(uint4*)&As[row][ch] = v;
        }
        #pragma unroll
        for (int r = 0; r < 2; r++) {
            int idx = tid + r * 256;
            int row = idx >> 2;
            int ch  = (idx & 3) * 8;
            uint4 v = make_uint4(0u, 0u, 0u, 0u);
            if (n0 + row < Brows)
                v = *(const uint4*)&Bg[(size_t)(n0 + row) * DIM + k0 + ch];
            *(uint4*)&Bs[row][ch] = v;
        }
        __syncthreads();

        // ---- two k16 steps per BK=32
        #pragma unroll
        for (int ks = 0; ks < 2; ks++) {
            const int kk = ks * 16 + tg * 2;
            uint32_t a[2][4];
            #pragma unroll
            for (int i = 0; i < 2; i++) {
                const int rr = wm + i * 16 + g;
                a[i][0] = *(const uint32_t*)&As[rr    ][kk    ];
                a[i][1] = *(const uint32_t*)&As[rr + 8][kk    ];
                a[i][2] = *(const uint32_t*)&As[rr    ][kk + 8];
                a[i][3] = *(const uint32_t*)&As[rr + 8][kk + 8];
            }
            #pragma unroll
            for (int j = 0; j < 8; j++) {
                const int cc = wn + j * 8 + g;
                uint32_t b0 = *(const uint32_t*)&Bs[cc][kk    ];
                uint32_t b1 = *(const uint32_t*)&Bs[cc][kk + 8];
                #pragma unroll
                for (int i = 0; i < 2; i++) {
                    asm volatile(
                        "mma.sync.aligned.m16n8k16.row.col.f32.bf16.bf16.f32 "
                        "{%0,%1,%2,%3}, {%4,%5,%6,%7}, {%8,%9}, {%0,%1,%2,%3};\n"
                        : "+f"(acc[i][j][0]), "+f"(acc[i][j][1]),
                          "+f"(acc[i][j][2]), "+f"(acc[i][j][3])
                        : "r"(a[i][0]), "r"(a[i][1]), "r"(a[i][2]), "r"(a[i][3]),
                          "r"(b0), "r"(b1));
                }
            }
        }
        __syncthreads();
    }
}

// ---------------------------------------------------------------------------
// GEMM1: Y[m,e] = featb[m,:] . Wb[e,:] + bias[e]   (fp32 out)
// ---------------------------------------------------------------------------
__global__ __launch_bounds__(256)
void proj_mma_kernel(const __nv_bfloat16* __restrict__ Ab,
                     const __nv_bfloat16* __restrict__ Wb,
                     const float* __restrict__ bias,
                     float* __restrict__ Y)
{
    __shared__ __nv_bfloat16 As[BM][LDT];
    __shared__ __nv_bfloat16 Bs[BN][LDT];

    const int m0 = blockIdx.y * BM;
    const int n0 = blockIdx.x * BN;

    float acc[2][8][4];
    #pragma unroll
    for (int i = 0; i < 2; i++)
        #pragma unroll
        for (int j = 0; j < 8; j++)
            #pragma unroll
            for (int e = 0; e < 4; e++) acc[i][j][e] = 0.f;

    mma_mainloop(Ab, Wb, m0, n0, DIM, acc, As, Bs);

    const int tid  = threadIdx.x;
    const int warp = tid >> 5;
    const int lane = tid & 31;
    const int wm = (warp & 3) * 32;
    const int wn = (warp >> 2) * 64;
    const int g  = lane >> 2;
    const int tg = lane & 3;

    #pragma unroll
    for (int j = 0; j < 8; j++) {
        const int nb = n0 + wn + j * 8 + tg * 2;
        const float b0 = bias[nb], b1 = bias[nb + 1];
        #pragma unroll
        for (int i = 0; i < 2; i++) {
            #pragma unroll
            for (int h = 0; h < 2; h++) {
                const int m = m0 + wm + i * 16 + g + h * 8;
                float2 v = make_float2(acc[i][j][2 * h + 0] + b0,
                                       acc[i][j][2 * h + 1] + b1);
                *(float2*)&Y[(size_t)m * DIM + nb] = v;
            }
        }
    }
}

// ---------------------------------------------------------------------------
// expmap0 per row (256 threads / row): fp32 in -> bf16 out + fp32 ||x||^2
// ---------------------------------------------------------------------------
__global__ void expmap_kernel(const float* __restrict__ src,
                              __nv_bfloat16* __restrict__ dst,
                              float* __restrict__ sq_out)
{
    const int row = blockIdx.x;
    const int tid = threadIdx.x;
    const float v = src[(size_t)row * DIM + tid];

    float s = v * v;
    #pragma unroll
    for (int off = 16; off > 0; off >>= 1)
        s += __shfl_xor_sync(0xFFFFFFFFu, s, off);

    __shared__ float warp_s[8];
    __shared__ float total_sh;
    const int warp = tid >> 5;
    if ((tid & 31) == 0) warp_s[warp] = s;
    __syncthreads();
    if (tid == 0) {
        float t = 0.f;
        #pragma unroll
        for (int w = 0; w < 8; w++) t += warp_s[w];
        total_sh = t;
    }
    __syncthreads();

    const float total = total_sh;
    const float norm  = sqrtf(total);
    const float cn    = fmaxf(norm, EPS_F);
    const float scale = tanhf(cn) / cn;

    dst[(size_t)row * DIM + tid] = __float2bfloat16(scale * v);
    if (tid == 0) sq_out[row] = scale * scale * total;
}

// ---------------------------------------------------------------------------
// GEMM2 + Poincare epilogue: out[m,c] = -acosh(arg)*lscale
// ---------------------------------------------------------------------------
__global__ __launch_bounds__(256)
void logits_mma_kernel(const __nv_bfloat16* __restrict__ Xb,
                       const __nv_bfloat16* __restrict__ Pb,
                       const float* __restrict__ xsq,
                       const float* __restrict__ psq,
                       const float* __restrict__ logit_scale,
                       float* __restrict__ Out)
{
    __shared__ __nv_bfloat16 As[BM][LDT];
    __shared__ __nv_bfloat16 Bs[BN][LDT];

    const int m0 = blockIdx.y * BM;
    const int n0 = blockIdx.x * BN;

    float acc[2][8][4];
    #pragma unroll
    for (int i = 0; i < 2; i++)
        #pragma unroll
        for (int j = 0; j < 8; j++)
            #pragma unroll
            for (int e = 0; e < 4; e++) acc[i][j][e] = 0.f;

    mma_mainloop(Xb, Pb, m0, n0, NCLS, acc, As, Bs);

    const int tid  = threadIdx.x;
    const int warp = tid >> 5;
    const int lane = tid & 31;
    const int wm = (warp & 3) * 32;
    const int wn = (warp >> 2) * 64;
    const int g  = lane >> 2;
    const int tg = lane & 3;

    const float lscale = fminf(expf(logit_scale[0]), 100.f);

    // per-thread row data: 4 distinct m values (i x h)
    float xs[2][2], one_m_xs[2][2];
    #pragma unroll
    for (int i = 0; i < 2; i++)
        #pragma unroll
        for (int h = 0; h < 2; h++) {
            const int m = m0 + wm + i * 16 + g + h * 8;
            xs[i][h] = xsq[m];
            one_m_xs[i][h] = 1.f - xs[i][h];
        }

    #pragma unroll
    for (int j = 0; j < 8; j++) {
        const int nb = n0 + wn + j * 8 + tg * 2;
        if (nb >= NCLS) continue;               // NCLS even -> pair in/out together
        const float ps0 = psq[nb], ps1 = psq[nb + 1];
        const float omp0 = 1.f - ps0, omp1 = 1.f - ps1;
        #pragma unroll
        for (int i = 0; i < 2; i++) {
            #pragma unroll
            for (int h = 0; h < 2; h++) {
                const int m = m0 + wm + i * 16 + g + h * 8;
                const float xsv = xs[i][h];
                const float omx = one_m_xs[i][h];

                float d0 = fmaxf(xsv + ps0 - 2.f * acc[i][j][2 * h + 0], 0.f);
                float d1 = fmaxf(xsv + ps1 - 2.f * acc[i][j][2 * h + 1], 0.f);
                float de0 = fmaxf(omx * omp0, EPS_F);
                float de1 = fmaxf(omx * omp1, EPS_F);
                float a0 = fmaxf(1.f + 2.f * d0 / de0, 1.f + EPS_F);
                float a1 = fmaxf(1.f + 2.f * d1 / de1, 1.f + EPS_F);
                // acosh(a) = log(a + sqrt(a*a - 1))
                float r0 = __logf(a0 + __fsqrt_rn(a0 * a0 - 1.f));
                float r1 = __logf(a1 + __fsqrt_rn(a1 * a1 - 1.f));
                float2 v = make_float2(-r0 * lscale, -r1 * lscale);
                *(float2*)&Out[(size_t)m * NCLS + nb] = v;
            }
        }
    }
}

// ---------------------------------------------------------------------------
// Launch
// Inputs: features[4,8192,256], W[256,256], b[256], embeddings[1000,256],
//         logit_scale[]   -> out float32 [4,8192,1000]
// ---------------------------------------------------------------------------
extern "C" void kernel_launch(void* const* d_in, const int* in_sizes, int n_in,
                              void* d_out, int out_size)
{
    const float* features    = (const float*)d_in[0];
    const float* W           = (const float*)d_in[1];
    const float* bias        = (const float*)d_in[2];
    const float* embeddings  = (const float*)d_in[3];
    const float* logit_scale = (const float*)d_in[4];
    float* out = (float*)d_out;

    __nv_bfloat16 *featb, *Wb, *xb, *pb;
    float *y, *xsq, *psq;
    cudaGetSymbolAddress((void**)&featb, g_featb);
    cudaGetSymbolAddress((void**)&Wb,    g_Wb);
    cudaGetSymbolAddress((void**)&y,     g_y);
    cudaGetSymbolAddress((void**)&xb,    g_xb);
    cudaGetSymbolAddress((void**)&xsq,   g_xsq);
    cudaGetSymbolAddress((void**)&pb,    g_pb);
    cudaGetSymbolAddress((void**)&psq,   g_psq);

    // 1. Convert inputs to bf16
    f2b_kernel<<<(MROWS * DIM / 4 + 255) / 256, 256>>>(features, featb, MROWS * DIM);
    f2b_kernel<<<(DIM * DIM / 4 + 255) / 256, 256>>>(W, Wb, DIM * DIM);

    // 2. Projection GEMM (bf16 MMA): y = feat @ W^T + b
    {
        dim3 grid(DIM / BN, MROWS / BM);      // (2, 256)
        proj_mma_kernel<<<grid, 256>>>(featb, Wb, bias, y);
    }

    // 3. expmap0 on projected features -> xb (bf16) + xsq
    expmap_kernel<<<MROWS, DIM>>>(y, xb, xsq);

    // 4. expmap0 on embeddings -> pb (bf16) + psq
    expmap_kernel<<<NCLS, DIM>>>(embeddings, pb, psq);

    // 5. Logits GEMM (bf16 MMA) + Poincare distance epilogue
    {
        dim3 grid((NCLS + BN - 1) / BN, MROWS / BM);   // (8, 256)
        logits_mma_kernel<<<grid, 256>>>(xb, pb, xsq, psq, logit_scale, out);
    }
}

// round 6
// speedup vs baseline: 4.2669x; 1.2570x over previous
#include <cuda_runtime.h>
#include <cuda_bf16.h>
#include <math.h>
#include <stdint.h>

// Problem constants
#define BATCH   4
#define SEQ     8192
#define MROWS   (BATCH * SEQ)   // 32768
#define DIM     256
#define NCLS    1000
#define EPS_F   1e-5f

// Logits GEMM tiling: 128x128 CTA, BK=32, 8 warps, warp tile 32x64
#define BM 128
#define BN 128
#define BK 32
#define LDS_PAD 8
#define LDT (BK + LDS_PAD)   // 40 halves -> 80B row stride, conflict-free frags

// Proj+expmap fused kernel tiling: 128x256 CTA (full output row), 16 warps
#define BMA 128
#define BNA 256

// Scratch
__device__ __nv_bfloat16 g_xb[MROWS * DIM];   // expmapped features (bf16)
__device__ float         g_xsq[MROWS];        // ||x||^2
__device__ __nv_bfloat16 g_pb[NCLS * DIM];    // expmapped prototypes (bf16)
__device__ float         g_psq[NCLS];         // ||p||^2

// ---------------------------------------------------------------------------
// cp.async helpers
// ---------------------------------------------------------------------------
__device__ __forceinline__ void cp16(void* dst_smem, const void* src, bool valid)
{
    uint32_t d = (uint32_t)__cvta_generic_to_shared(dst_smem);
    int sz = valid ? 16 : 0;
    asm volatile("cp.async.cg.shared.global [%0], [%1], 16, %2;\n"
                 :: "r"(d), "l"(src), "r"(sz));
}
#define CP_COMMIT() asm volatile("cp.async.commit_group;\n" ::: "memory")

// ---------------------------------------------------------------------------
// Fused: features(fp32) @ W^T + b  ->  expmap0  ->  xb (bf16), xsq (fp32)
// CTA tile 128 x 256 (full row of the projection output), 512 threads.
// Warp grid 4(M) x 4(N); warp tile 32 x 64. m16n8k16 bf16 MMA.
// ---------------------------------------------------------------------------
__global__ __launch_bounds__(512)
void proj_expmap_kernel(const float* __restrict__ A,     // [MROWS, 256] fp32
                        const float* __restrict__ W,     // [256, 256] fp32
                        const float* __restrict__ bias,  // [256]
                        __nv_bfloat16* __restrict__ Xb,
                        float* __restrict__ xsq_out)
{
    __shared__ __nv_bfloat16 As[BMA][LDT];
    __shared__ __nv_bfloat16 Bs[BNA][LDT];
    __shared__ float rowsum[BMA];
    __shared__ float rowscale[BMA];

    const int tid = threadIdx.x;          // 512
    const int m0  = blockIdx.x * BMA;

    if (tid < BMA) rowsum[tid] = 0.f;

    const int warp = tid >> 5;            // 0..15
    const int lane = tid & 31;
    const int wm = (warp & 3) * 32;
    const int wn = (warp >> 2) * 64;
    const int g  = lane >> 2;
    const int tg = lane & 3;

    float acc[2][8][4];
    #pragma unroll
    for (int i = 0; i < 2; i++)
        #pragma unroll
        for (int j = 0; j < 8; j++)
            #pragma unroll
            for (int e = 0; e < 4; e++) acc[i][j][e] = 0.f;

    for (int k0 = 0; k0 < DIM; k0 += BK) {
        // A: 128 rows x 32 fp32 -> convert -> As.  1024 float4 slots, 2/thread.
        #pragma unroll
        for (int r = 0; r < 2; r++) {
            int idx = tid + r * 512;
            int row = idx >> 3;
            int ch  = (idx & 7) * 4;
            float4 v = *(const float4*)&A[(size_t)(m0 + row) * DIM + k0 + ch];
            __nv_bfloat162 lo = __floats2bfloat162_rn(v.x, v.y);
            __nv_bfloat162 hi = __floats2bfloat162_rn(v.z, v.w);
            uint2 pk; pk.x = *(uint32_t*)&lo; pk.y = *(uint32_t*)&hi;
            *(uint2*)&As[row][ch] = pk;
        }
        // B (W): 256 rows x 32 fp32 -> Bs.  2048 slots, 4/thread.
        #pragma unroll
        for (int r = 0; r < 4; r++) {
            int idx = tid + r * 512;
            int row = idx >> 3;
            int ch  = (idx & 7) * 4;
            float4 v = *(const float4*)&W[(size_t)row * DIM + k0 + ch];
            __nv_bfloat162 lo = __floats2bfloat162_rn(v.x, v.y);
            __nv_bfloat162 hi = __floats2bfloat162_rn(v.z, v.w);
            uint2 pk; pk.x = *(uint32_t*)&lo; pk.y = *(uint32_t*)&hi;
            *(uint2*)&Bs[row][ch] = pk;
        }
        __syncthreads();

        #pragma unroll
        for (int ks = 0; ks < 2; ks++) {
            const int kk = ks * 16 + tg * 2;
            uint32_t a[2][4];
            #pragma unroll
            for (int i = 0; i < 2; i++) {
                const int rr = wm + i * 16 + g;
                a[i][0] = *(const uint32_t*)&As[rr    ][kk    ];
                a[i][1] = *(const uint32_t*)&As[rr + 8][kk    ];
                a[i][2] = *(const uint32_t*)&As[rr    ][kk + 8];
                a[i][3] = *(const uint32_t*)&As[rr + 8][kk + 8];
            }
            #pragma unroll
            for (int j = 0; j < 8; j++) {
                const int cc = wn + j * 8 + g;
                uint32_t b0 = *(const uint32_t*)&Bs[cc][kk    ];
                uint32_t b1 = *(const uint32_t*)&Bs[cc][kk + 8];
                #pragma unroll
                for (int i = 0; i < 2; i++) {
                    asm volatile(
                        "mma.sync.aligned.m16n8k16.row.col.f32.bf16.bf16.f32 "
                        "{%0,%1,%2,%3}, {%4,%5,%6,%7}, {%8,%9}, {%0,%1,%2,%3};\n"
                        : "+f"(acc[i][j][0]), "+f"(acc[i][j][1]),
                          "+f"(acc[i][j][2]), "+f"(acc[i][j][3])
                        : "r"(a[i][0]), "r"(a[i][1]), "r"(a[i][2]), "r"(a[i][3]),
                          "r"(b0), "r"(b1));
                }
            }
        }
        __syncthreads();
    }

    // ---- epilogue: bias add, row sum of squares, expmap, write bf16 + xsq
    float part[2][2] = {{0.f, 0.f}, {0.f, 0.f}};
    #pragma unroll
    for (int j = 0; j < 8; j++) {
        const int nb = wn + j * 8 + tg * 2;
        const float b0 = bias[nb], b1 = bias[nb + 1];
        #pragma unroll
        for (int i = 0; i < 2; i++) {
            #pragma unroll
            for (int h = 0; h < 2; h++) {
                float y0 = acc[i][j][2 * h + 0] + b0;
                float y1 = acc[i][j][2 * h + 1] + b1;
                acc[i][j][2 * h + 0] = y0;
                acc[i][j][2 * h + 1] = y1;
                part[i][h] += y0 * y0 + y1 * y1;
            }
        }
    }
    #pragma unroll
    for (int i = 0; i < 2; i++)
        #pragma unroll
        for (int h = 0; h < 2; h++)
            atomicAdd(&rowsum[wm + i * 16 + g + h * 8], part[i][h]);
    __syncthreads();

    if (tid < BMA) {
        const float total = rowsum[tid];
        const float norm  = sqrtf(total);
        const float cn    = fmaxf(norm, EPS_F);
        const float s     = tanhf(cn) / cn;
        rowscale[tid] = s;
        xsq_out[m0 + tid] = s * s * total;
    }
    __syncthreads();

    #pragma unroll
    for (int i = 0; i < 2; i++) {
        #pragma unroll
        for (int h = 0; h < 2; h++) {
            const int ml = wm + i * 16 + g + h * 8;
            const float s = rowscale[ml];
            const int m = m0 + ml;
            #pragma unroll
            for (int j = 0; j < 8; j++) {
                const int nb = wn + j * 8 + tg * 2;
                __nv_bfloat162 v = __floats2bfloat162_rn(
                    s * acc[i][j][2 * h + 0], s * acc[i][j][2 * h + 1]);
                *(__nv_bfloat162*)&Xb[(size_t)m * DIM + nb] = v;
            }
        }
    }
}

// ---------------------------------------------------------------------------
// expmap0 for embeddings (fp32 in -> bf16 out + ||p||^2), one block per row
// ---------------------------------------------------------------------------
__global__ void expmap_kernel(const float* __restrict__ src,
                              __nv_bfloat16* __restrict__ dst,
                              float* __restrict__ sq_out)
{
    const int row = blockIdx.x;
    const int tid = threadIdx.x;
    const float v = src[(size_t)row * DIM + tid];

    float s = v * v;
    #pragma unroll
    for (int off = 16; off > 0; off >>= 1)
        s += __shfl_xor_sync(0xFFFFFFFFu, s, off);

    __shared__ float warp_s[8];
    __shared__ float total_sh;
    const int warp = tid >> 5;
    if ((tid & 31) == 0) warp_s[warp] = s;
    __syncthreads();
    if (tid == 0) {
        float t = 0.f;
        #pragma unroll
        for (int w = 0; w < 8; w++) t += warp_s[w];
        total_sh = t;
    }
    __syncthreads();

    const float total = total_sh;
    const float norm  = sqrtf(total);
    const float cn    = fmaxf(norm, EPS_F);
    const float scale = tanhf(cn) / cn;

    dst[(size_t)row * DIM + tid] = __float2bfloat16(scale * v);
    if (tid == 0) sq_out[row] = scale * scale * total;
}

// ---------------------------------------------------------------------------
// Logits GEMM (cp.async double-buffered) + Poincare epilogue
// ---------------------------------------------------------------------------
__global__ __launch_bounds__(256)
void logits_mma_kernel(const __nv_bfloat16* __restrict__ Xb,
                       const __nv_bfloat16* __restrict__ Pb,
                       const float* __restrict__ xsq,
                       const float* __restrict__ psq,
                       const float* __restrict__ logit_scale,
                       float* __restrict__ Out)
{
    __shared__ __nv_bfloat16 As[2][BM][LDT];
    __shared__ __nv_bfloat16 Bs[2][BN][LDT];

    const int tid  = threadIdx.x;
    const int m0 = blockIdx.y * BM;
    const int n0 = blockIdx.x * BN;

    const int warp = tid >> 5;
    const int lane = tid & 31;
    const int wm = (warp & 3) * 32;
    const int wn = (warp >> 2) * 64;
    const int g  = lane >> 2;
    const int tg = lane & 3;

    // per-thread load coords: 128 rows x 2 x 16B per operand
    const int lrow = tid >> 2;            // 0..63 (+64 on r=1)
    const int lch  = (tid & 3) * 8;

    float acc[2][8][4];
    #pragma unroll
    for (int i = 0; i < 2; i++)
        #pragma unroll
        for (int j = 0; j < 8; j++)
            #pragma unroll
            for (int e = 0; e < 4; e++) acc[i][j][e] = 0.f;

    // ---- prologue: load stage 0
    {
        const int k0 = 0;
        #pragma unroll
        for (int r = 0; r < 2; r++) {
            int row = lrow + r * 64;
            cp16(&As[0][row][lch], &Xb[(size_t)(m0 + row) * DIM + k0 + lch], true);
        }
        #pragma unroll
        for (int r = 0; r < 2; r++) {
            int row = lrow + r * 64;
            cp16(&Bs[0][row][lch], &Pb[(size_t)(n0 + row) * DIM + k0 + lch],
                 (n0 + row) < NCLS);
        }
        CP_COMMIT();
    }

    const int NKT = DIM / BK;   // 8
    for (int kt = 0; kt < NKT; kt++) {
        if (kt + 1 < NKT) {
            const int k0 = (kt + 1) * BK;
            const int st = (kt + 1) & 1;
            #pragma unroll
            for (int r = 0; r < 2; r++) {
                int row = lrow + r * 64;
                cp16(&As[st][row][lch], &Xb[(size_t)(m0 + row) * DIM + k0 + lch], true);
            }
            #pragma unroll
            for (int r = 0; r < 2; r++) {
                int row = lrow + r * 64;
                cp16(&Bs[st][row][lch], &Pb[(size_t)(n0 + row) * DIM + k0 + lch],
                     (n0 + row) < NCLS);
            }
            CP_COMMIT();
            asm volatile("cp.async.wait_group 1;\n" ::: "memory");
        } else {
            asm volatile("cp.async.wait_group 0;\n" ::: "memory");
        }
        __syncthreads();

        const int st = kt & 1;
        #pragma unroll
        for (int ks = 0; ks < 2; ks++) {
            const int kk = ks * 16 + tg * 2;
            uint32_t a[2][4];
            #pragma unroll
            for (int i = 0; i < 2; i++) {
                const int rr = wm + i * 16 + g;
                a[i][0] = *(const uint32_t*)&As[st][rr    ][kk    ];
                a[i][1] = *(const uint32_t*)&As[st][rr + 8][kk    ];
                a[i][2] = *(const uint32_t*)&As[st][rr    ][kk + 8];
                a[i][3] = *(const uint32_t*)&As[st][rr + 8][kk + 8];
            }
            #pragma unroll
            for (int j = 0; j < 8; j++) {
                const int cc = wn + j * 8 + g;
                uint32_t b0 = *(const uint32_t*)&Bs[st][cc][kk    ];
                uint32_t b1 = *(const uint32_t*)&Bs[st][cc][kk + 8];
                #pragma unroll
                for (int i = 0; i < 2; i++) {
                    asm volatile(
                        "mma.sync.aligned.m16n8k16.row.col.f32.bf16.bf16.f32 "
                        "{%0,%1,%2,%3}, {%4,%5,%6,%7}, {%8,%9}, {%0,%1,%2,%3};\n"
                        : "+f"(acc[i][j][0]), "+f"(acc[i][j][1]),
                          "+f"(acc[i][j][2]), "+f"(acc[i][j][3])
                        : "r"(a[i][0]), "r"(a[i][1]), "r"(a[i][2]), "r"(a[i][3]),
                          "r"(b0), "r"(b1));
                }
            }
        }
        __syncthreads();
    }

    // ---- Poincare epilogue
    const float lscale = fminf(expf(logit_scale[0]), 100.f);

    float xs[2][2], one_m_xs[2][2];
    #pragma unroll
    for (int i = 0; i < 2; i++)
        #pragma unroll
        for (int h = 0; h < 2; h++) {
            const int m = m0 + wm + i * 16 + g + h * 8;
            xs[i][h] = xsq[m];
            one_m_xs[i][h] = 1.f - xs[i][h];
        }

    #pragma unroll
    for (int j = 0; j < 8; j++) {
        const int nb = n0 + wn + j * 8 + tg * 2;
        if (nb >= NCLS) continue;              // NCLS even -> pairs in/out together
        const float ps0 = psq[nb], ps1 = psq[nb + 1];
        const float omp0 = 1.f - ps0, omp1 = 1.f - ps1;
        #pragma unroll
        for (int i = 0; i < 2; i++) {
            #pragma unroll
            for (int h = 0; h < 2; h++) {
                const int m = m0 + wm + i * 16 + g + h * 8;
                const float xsv = xs[i][h];
                const float omx = one_m_xs[i][h];

                float d0 = fmaxf(xsv + ps0 - 2.f * acc[i][j][2 * h + 0], 0.f);
                float d1 = fmaxf(xsv + ps1 - 2.f * acc[i][j][2 * h + 1], 0.f);
                float de0 = fmaxf(omx * omp0, EPS_F);
                float de1 = fmaxf(omx * omp1, EPS_F);
                float a0 = fmaxf(1.f + 2.f * d0 / de0, 1.f + EPS_F);
                float a1 = fmaxf(1.f + 2.f * d1 / de1, 1.f + EPS_F);
                float r0 = __logf(a0 + __fsqrt_rn(a0 * a0 - 1.f));
                float r1 = __logf(a1 + __fsqrt_rn(a1 * a1 - 1.f));
                float2 v = make_float2(-r0 * lscale, -r1 * lscale);
                *(float2*)&Out[(size_t)m * NCLS + nb] = v;
            }
        }
    }
}

// ---------------------------------------------------------------------------
// Launch
// ---------------------------------------------------------------------------
extern "C" void kernel_launch(void* const* d_in, const int* in_sizes, int n_in,
                              void* d_out, int out_size)
{
    const float* features    = (const float*)d_in[0];
    const float* W           = (const float*)d_in[1];
    const float* bias        = (const float*)d_in[2];
    const float* embeddings  = (const float*)d_in[3];
    const float* logit_scale = (const float*)d_in[4];
    float* out = (float*)d_out;

    __nv_bfloat16 *xb, *pb;
    float *xsq, *psq;
    cudaGetSymbolAddress((void**)&xb,  g_xb);
    cudaGetSymbolAddress((void**)&xsq, g_xsq);
    cudaGetSymbolAddress((void**)&pb,  g_pb);
    cudaGetSymbolAddress((void**)&psq, g_psq);

    // 1. Fused: convert + projection GEMM + expmap0 -> xb, xsq
    proj_expmap_kernel<<<MROWS / BMA, 512>>>(features, W, bias, xb, xsq);

    // 2. expmap0 on embeddings -> pb, psq
    expmap_kernel<<<NCLS, DIM>>>(embeddings, pb, psq);

    // 3. Logits GEMM (pipelined) + Poincare epilogue
    {
        dim3 grid((NCLS + BN - 1) / BN, MROWS / BM);   // (8, 256)
        logits_mma_kernel<<<grid, 256>>>(xb, pb, xsq, psq, logit_scale, out);
    }
}

// round 8
// speedup vs baseline: 4.6907x; 1.0993x over previous
#include <cuda_runtime.h>
#include <cuda_bf16.h>
#include <math.h>
#include <stdint.h>

// Problem constants
#define BATCH   4
#define SEQ     8192
#define MROWS   (BATCH * SEQ)   // 32768
#define DIM     256
#define NCLS    1000
#define EPS_F   1e-5f

// Shared tiling
#define BK  32
#define LDS_PAD 8
#define LDT (BK + LDS_PAD)      // 40 halves = 80B row stride (16B-aligned, bank-clean)

// Proj+expmap fused kernel tiling: 128x256 CTA, 16 warps (4M x 4N), warp 32x64
#define BMA 128
#define BNA 256

// Logits: 128x128 CTA, 8 warps (4M x 2N), warp 32x64, 3-stage cp.async
#define BM 128
#define BN 128
#define STG 3
#define STG_HALVES (BM * LDT)               // per-operand per-stage halves
#define STG_BYTES  (STG_HALVES * 2)         // 10240 B
#define LOGITS_SMEM (STG * 2 * STG_BYTES)   // 61440 B

// Scratch
__device__ __nv_bfloat16 g_xb[MROWS * DIM];   // expmapped features (bf16)
__device__ float         g_xsq[MROWS];        // ||x||^2
__device__ __nv_bfloat16 g_pb[NCLS * DIM];    // expmapped prototypes (bf16)
__device__ float         g_psq[NCLS];         // ||p||^2

// ---------------------------------------------------------------------------
// PTX helpers (base-sm_103-legal only: cp.async, ldmatrix, mma.sync)
// ---------------------------------------------------------------------------
__device__ __forceinline__ uint32_t smem_u32(const void* p) {
    return (uint32_t)__cvta_generic_to_shared(p);
}
__device__ __forceinline__ void cp16s(uint32_t dst_saddr, const void* src, bool valid)
{
    int sz = valid ? 16 : 0;
    asm volatile("cp.async.cg.shared.global [%0], [%1], 16, %2;\n"
                 :: "r"(dst_saddr), "l"(src), "r"(sz));
}
#define CP_COMMIT() asm volatile("cp.async.commit_group;\n" ::: "memory")

__device__ __forceinline__ void ldm_x4(uint32_t& r0, uint32_t& r1,
                                       uint32_t& r2, uint32_t& r3, uint32_t saddr)
{
    asm volatile("ldmatrix.sync.aligned.m8n8.x4.shared.b16 {%0,%1,%2,%3}, [%4];"
                 : "=r"(r0), "=r"(r1), "=r"(r2), "=r"(r3) : "r"(saddr));
}

__device__ __forceinline__ void mma16816(float acc[4], uint32_t a0, uint32_t a1,
                                         uint32_t a2, uint32_t a3,
                                         uint32_t b0, uint32_t b1)
{
    asm volatile(
        "mma.sync.aligned.m16n8k16.row.col.f32.bf16.bf16.f32 "
        "{%0,%1,%2,%3}, {%4,%5,%6,%7}, {%8,%9}, {%0,%1,%2,%3};\n"
        : "+f"(acc[0]), "+f"(acc[1]), "+f"(acc[2]), "+f"(acc[3])
        : "r"(a0), "r"(a1), "r"(a2), "r"(a3), "r"(b0), "r"(b1));
}

// ---------------------------------------------------------------------------
// Fused: features(fp32) @ W^T + b  ->  expmap0  ->  xb (bf16), xsq (fp32)
// ---------------------------------------------------------------------------
__global__ __launch_bounds__(512)
void proj_expmap_kernel(const float* __restrict__ A,
                        const float* __restrict__ W,
                        const float* __restrict__ bias,
                        __nv_bfloat16* __restrict__ Xb,
                        float* __restrict__ xsq_out)
{
    __shared__ __nv_bfloat16 As[BMA][LDT];
    __shared__ __nv_bfloat16 Bs[BNA][LDT];
    __shared__ float rowsum[BMA];
    __shared__ float rowscale[BMA];

    const int tid = threadIdx.x;          // 512
    const int m0  = blockIdx.x * BMA;

    if (tid < BMA) rowsum[tid] = 0.f;

    const int warp = tid >> 5;            // 0..15
    const int lane = tid & 31;
    const int wm = (warp & 3) * 32;
    const int wn = (warp >> 2) * 64;
    const int g  = lane >> 2;
    const int tg = lane & 3;
    const int lrow16 = lane & 15;
    const int khalf  = (lane >> 4) << 3;

    const uint32_t asb = smem_u32(&As[0][0]);
    const uint32_t bsb = smem_u32(&Bs[0][0]);

    float acc[2][8][4];
    #pragma unroll
    for (int i = 0; i < 2; i++)
        #pragma unroll
        for (int j = 0; j < 8; j++)
            #pragma unroll
            for (int e = 0; e < 4; e++) acc[i][j][e] = 0.f;

    for (int k0 = 0; k0 < DIM; k0 += BK) {
        // A: 128 rows x 32 fp32 -> convert -> As
        #pragma unroll
        for (int r = 0; r < 2; r++) {
            int idx = tid + r * 512;
            int row = idx >> 3;
            int ch  = (idx & 7) * 4;
            float4 v = *(const float4*)&A[(size_t)(m0 + row) * DIM + k0 + ch];
            __nv_bfloat162 lo = __floats2bfloat162_rn(v.x, v.y);
            __nv_bfloat162 hi = __floats2bfloat162_rn(v.z, v.w);
            uint2 pk; pk.x = *(uint32_t*)&lo; pk.y = *(uint32_t*)&hi;
            *(uint2*)&As[row][ch] = pk;
        }
        // W: 256 rows x 32 fp32 -> Bs
        #pragma unroll
        for (int r = 0; r < 4; r++) {
            int idx = tid + r * 512;
            int row = idx >> 3;
            int ch  = (idx & 7) * 4;
            float4 v = *(const float4*)&W[(size_t)row * DIM + k0 + ch];
            __nv_bfloat162 lo = __floats2bfloat162_rn(v.x, v.y);
            __nv_bfloat162 hi = __floats2bfloat162_rn(v.z, v.w);
            uint2 pk; pk.x = *(uint32_t*)&lo; pk.y = *(uint32_t*)&hi;
            *(uint2*)&Bs[row][ch] = pk;
        }
        __syncthreads();

        #pragma unroll
        for (int ks = 0; ks < 2; ks++) {
            const int kc = ks * 16 + khalf;
            uint32_t a[2][4];
            #pragma unroll
            for (int i = 0; i < 2; i++)
                ldm_x4(a[i][0], a[i][1], a[i][2], a[i][3],
                       asb + (uint32_t)((wm + i * 16 + lrow16) * LDT + kc) * 2u);
            #pragma unroll
            for (int jj = 0; jj < 4; jj++) {
                uint32_t b0, b1, b2, b3;
                ldm_x4(b0, b1, b2, b3,
                       bsb + (uint32_t)((wn + jj * 16 + lrow16) * LDT + kc) * 2u);
                #pragma unroll
                for (int i = 0; i < 2; i++) {
                    mma16816(acc[i][2 * jj + 0], a[i][0], a[i][1], a[i][2], a[i][3], b0, b2);
                    mma16816(acc[i][2 * jj + 1], a[i][0], a[i][1], a[i][2], a[i][3], b1, b3);
                }
            }
        }
        __syncthreads();
    }

    // epilogue: bias, row sumsq, expmap, write bf16 + xsq
    float part[2][2] = {{0.f, 0.f}, {0.f, 0.f}};
    #pragma unroll
    for (int j = 0; j < 8; j++) {
        const int nb = wn + j * 8 + tg * 2;
        const float b0 = bias[nb], b1 = bias[nb + 1];
        #pragma unroll
        for (int i = 0; i < 2; i++) {
            #pragma unroll
            for (int h = 0; h < 2; h++) {
                float y0 = acc[i][j][2 * h + 0] + b0;
                float y1 = acc[i][j][2 * h + 1] + b1;
                acc[i][j][2 * h + 0] = y0;
                acc[i][j][2 * h + 1] = y1;
                part[i][h] += y0 * y0 + y1 * y1;
            }
        }
    }
    #pragma unroll
    for (int i = 0; i < 2; i++)
        #pragma unroll
        for (int h = 0; h < 2; h++)
            atomicAdd(&rowsum[wm + i * 16 + g + h * 8], part[i][h]);
    __syncthreads();

    if (tid < BMA) {
        const float total = rowsum[tid];
        const float norm  = sqrtf(total);
        const float cn    = fmaxf(norm, EPS_F);
        const float s     = tanhf(cn) / cn;
        rowscale[tid] = s;
        xsq_out[m0 + tid] = s * s * total;
    }
    __syncthreads();

    #pragma unroll
    for (int i = 0; i < 2; i++) {
        #pragma unroll
        for (int h = 0; h < 2; h++) {
            const int ml = wm + i * 16 + g + h * 8;
            const float s = rowscale[ml];
            const int m = m0 + ml;
            #pragma unroll
            for (int j = 0; j < 8; j++) {
                const int nb = wn + j * 8 + tg * 2;
                __nv_bfloat162 v = __floats2bfloat162_rn(
                    s * acc[i][j][2 * h + 0], s * acc[i][j][2 * h + 1]);
                *(__nv_bfloat162*)&Xb[(size_t)m * DIM + nb] = v;
            }
        }
    }
}

// ---------------------------------------------------------------------------
// expmap0 for embeddings
// ---------------------------------------------------------------------------
__global__ void expmap_kernel(const float* __restrict__ src,
                              __nv_bfloat16* __restrict__ dst,
                              float* __restrict__ sq_out)
{
    const int row = blockIdx.x;
    const int tid = threadIdx.x;
    const float v = src[(size_t)row * DIM + tid];

    float s = v * v;
    #pragma unroll
    for (int off = 16; off > 0; off >>= 1)
        s += __shfl_xor_sync(0xFFFFFFFFu, s, off);

    __shared__ float warp_s[8];
    __shared__ float total_sh;
    const int warp = tid >> 5;
    if ((tid & 31) == 0) warp_s[warp] = s;
    __syncthreads();
    if (tid == 0) {
        float t = 0.f;
        #pragma unroll
        for (int w = 0; w < 8; w++) t += warp_s[w];
        total_sh = t;
    }
    __syncthreads();

    const float total = total_sh;
    const float norm  = sqrtf(total);
    const float cn    = fmaxf(norm, EPS_F);
    const float scale = tanhf(cn) / cn;

    dst[(size_t)row * DIM + tid] = __float2bfloat16(scale * v);
    if (tid == 0) sq_out[row] = scale * scale * total;
}

// ---------------------------------------------------------------------------
// Logits GEMM: 3-stage cp.async pipeline + ldmatrix + HMMA + Poincare epilogue
// ---------------------------------------------------------------------------
__global__ __launch_bounds__(256, 2)
void logits_mma_kernel(const __nv_bfloat16* __restrict__ Xb,
                       const __nv_bfloat16* __restrict__ Pb,
                       const float* __restrict__ xsq,
                       const float* __restrict__ psq,
                       const float* __restrict__ logit_scale,
                       float* __restrict__ Out)
{
    extern __shared__ __nv_bfloat16 dsm[];
    const uint32_t base = smem_u32(dsm);
    // layout: A stages [0..STG), then B stages
    const uint32_t aoff[STG] = {0u, STG_BYTES, 2u * STG_BYTES};
    const uint32_t boff0 = STG * STG_BYTES;

    const int tid  = threadIdx.x;
    const int m0 = blockIdx.y * BM;
    const int n0 = blockIdx.x * BN;

    const int warp = tid >> 5;
    const int lane = tid & 31;
    const int wm = (warp & 3) * 32;
    const int wn = (warp >> 2) * 64;
    const int g  = lane >> 2;
    const int tg = lane & 3;
    const int lrow16 = lane & 15;
    const int khalf  = (lane >> 4) << 3;

    // loader coords: 128 rows x 2 x 16B per operand, 256 threads
    const int lrow = tid >> 2;            // 0..63 (+64)
    const int lch  = (tid & 3) * 8;       // halves

    float acc[2][8][4];
    #pragma unroll
    for (int i = 0; i < 2; i++)
        #pragma unroll
        for (int j = 0; j < 8; j++)
            #pragma unroll
            for (int e = 0; e < 4; e++) acc[i][j][e] = 0.f;

    const int NKT = DIM / BK;   // 8

    // stage loader
    auto load_stage = [&](int kt, int st) {
        const int k0 = kt * BK;
        #pragma unroll
        for (int r = 0; r < 2; r++) {
            int row = lrow + r * 64;
            uint32_t d = (uint32_t)(row * LDT + lch) * 2u;
            cp16s(base + aoff[st] + d,
                  &Xb[(size_t)(m0 + row) * DIM + k0 + lch], true);
            cp16s(base + boff0 + aoff[st] + d,
                  &Pb[(size_t)(n0 + row) * DIM + k0 + lch], (n0 + row) < NCLS);
        }
        CP_COMMIT();
    };

    load_stage(0, 0);
    load_stage(1, 1);

    for (int kt = 0; kt < NKT; kt++) {
        if (kt + 2 < NKT)
            asm volatile("cp.async.wait_group 1;\n" ::: "memory");
        else
            asm volatile("cp.async.wait_group 0;\n" ::: "memory");
        __syncthreads();

        if (kt + 2 < NKT) load_stage(kt + 2, (kt + 2) % STG);

        const int st = kt % STG;
        const uint32_t ab = base + aoff[st];
        const uint32_t bb = base + boff0 + aoff[st];

        #pragma unroll
        for (int ks = 0; ks < 2; ks++) {
            const int kc = ks * 16 + khalf;
            uint32_t a[2][4];
            #pragma unroll
            for (int i = 0; i < 2; i++)
                ldm_x4(a[i][0], a[i][1], a[i][2], a[i][3],
                       ab + (uint32_t)((wm + i * 16 + lrow16) * LDT + kc) * 2u);
            #pragma unroll
            for (int jj = 0; jj < 4; jj++) {
                uint32_t b0, b1, b2, b3;
                ldm_x4(b0, b1, b2, b3,
                       bb + (uint32_t)((wn + jj * 16 + lrow16) * LDT + kc) * 2u);
                #pragma unroll
                for (int i = 0; i < 2; i++) {
                    mma16816(acc[i][2 * jj + 0], a[i][0], a[i][1], a[i][2], a[i][3], b0, b2);
                    mma16816(acc[i][2 * jj + 1], a[i][0], a[i][1], a[i][2], a[i][3], b1, b3);
                }
            }
        }
        __syncthreads();
    }

    // ---- Poincare epilogue
    const float lscale = fminf(expf(logit_scale[0]), 100.f);

    float xs[2][2], one_m_xs[2][2];
    #pragma unroll
    for (int i = 0; i < 2; i++)
        #pragma unroll
        for (int h = 0; h < 2; h++) {
            const int m = m0 + wm + i * 16 + g + h * 8;
            xs[i][h] = xsq[m];
            one_m_xs[i][h] = 1.f - xs[i][h];
        }

    #pragma unroll
    for (int j = 0; j < 8; j++) {
        const int nb = n0 + wn + j * 8 + tg * 2;
        if (nb >= NCLS) continue;              // NCLS even -> pairs in/out together
        const float ps0 = psq[nb], ps1 = psq[nb + 1];
        const float omp0 = 1.f - ps0, omp1 = 1.f - ps1;
        #pragma unroll
        for (int i = 0; i < 2; i++) {
            #pragma unroll
            for (int h = 0; h < 2; h++) {
                const int m = m0 + wm + i * 16 + g + h * 8;
                const float xsv = xs[i][h];
                const float omx = one_m_xs[i][h];

                float d0 = fmaxf(xsv + ps0 - 2.f * acc[i][j][2 * h + 0], 0.f);
                float d1 = fmaxf(xsv + ps1 - 2.f * acc[i][j][2 * h + 1], 0.f);
                float de0 = fmaxf(omx * omp0, EPS_F);
                float de1 = fmaxf(omx * omp1, EPS_F);
                float a0 = fmaxf(1.f + 2.f * d0 / de0, 1.f + EPS_F);
                float a1 = fmaxf(1.f + 2.f * d1 / de1, 1.f + EPS_F);
                float r0 = __logf(a0 + __fsqrt_rn(a0 * a0 - 1.f));
                float r1 = __logf(a1 + __fsqrt_rn(a1 * a1 - 1.f));
                float2 v = make_float2(-r0 * lscale, -r1 * lscale);
                *(float2*)&Out[(size_t)m * NCLS + nb] = v;
            }
        }
    }
}

// ---------------------------------------------------------------------------
// Launch
// ---------------------------------------------------------------------------
extern "C" void kernel_launch(void* const* d_in, const int* in_sizes, int n_in,
                              void* d_out, int out_size)
{
    const float* features    = (const float*)d_in[0];
    const float* W           = (const float*)d_in[1];
    const float* bias        = (const float*)d_in[2];
    const float* embeddings  = (const float*)d_in[3];
    const float* logit_scale = (const float*)d_in[4];
    float* out = (float*)d_out;

    __nv_bfloat16 *xb, *pb;
    float *xsq, *psq;
    cudaGetSymbolAddress((void**)&xb,  g_xb);
    cudaGetSymbolAddress((void**)&xsq, g_xsq);
    cudaGetSymbolAddress((void**)&pb,  g_pb);
    cudaGetSymbolAddress((void**)&psq, g_psq);

    // 1. Fused: convert + projection GEMM + expmap0 -> xb, xsq
    proj_expmap_kernel<<<MROWS / BMA, 512>>>(features, W, bias, xb, xsq);

    // 2. expmap0 on embeddings -> pb, psq
    expmap_kernel<<<NCLS, DIM>>>(embeddings, pb, psq);

    // 3. Logits GEMM (3-stage pipeline, ldmatrix) + Poincare epilogue
    cudaFuncSetAttribute(logits_mma_kernel,
                         cudaFuncAttributeMaxDynamicSharedMemorySize, LOGITS_SMEM);
    {
        dim3 grid((NCLS + BN - 1) / BN, MROWS / BM);   // (8, 256)
        logits_mma_kernel<<<grid, 256, LOGITS_SMEM>>>(xb, pb, xsq, psq,
                                                      logit_scale, out);
    }
}